// round 2
// baseline (speedup 1.0000x reference)
#include <cuda_runtime.h>
#include <cuda_bf16.h>

// Config: warp = 4 images x 8 segments; block = 8 warps = 32 images; grid = 256.
#define W2_STRIDE 11                  // 10 outputs padded to 11
#define W2_FLOATS (784 * W2_STRIDE)   // 8624 floats = 34.5 KB
#define IMGS_PER_BLOCK 32
#define B_TOTAL 8192
#define GRID (B_TOTAL / IMGS_PER_BLOCK)   // 256

// Scratch (no allocation allowed)
__device__ float g_W2[W2_FLOATS];   // [i=4p+j][o], stride 11
__device__ float g_b2[10];
__device__ float g_trig[16];        // cv0[0..3] sv0[4..7] cw[8..11] sw[12..15]

// ---------------------------------------------------------------------------
// Setup: fold map_w into lin_w (W2), fold map_b/lin_b into b2, precompute trig
// ---------------------------------------------------------------------------
__global__ void setup_kernel(const float* __restrict__ var_params,
                             const float* __restrict__ map_w,
                             const float* __restrict__ map_b,
                             const float* __restrict__ lin_w,
                             const float* __restrict__ lin_b) {
    int blk = blockIdx.x;
    int tid = threadIdx.x;
    if (blk < 31) {
        int idx = blk * 256 + tid;          // 0..7839 -> (i, o)
        if (idx < 7840) {
            int i = idx / 10;
            int o = idx - i * 10;
            int p = i >> 2;
            int j = i & 3;
            const float* lw = lin_w + o * 1568 + 8 * p;
            float acc = 0.0f;
#pragma unroll
            for (int k = 0; k < 8; k++)
                acc += lw[k] * map_w[k * 4 + j];
            g_W2[i * W2_STRIDE + o] = acc;
        }
    } else if (blk == 31) {
        // b2[o] = lin_b[o] + sum_t lin_w[o, t] * map_b[t % 8]
        int w = tid >> 5, lane = tid & 31;
        for (int o = w; o < 10; o += 8) {
            float acc = 0.0f;
            for (int t = lane; t < 1568; t += 32)
                acc += lin_w[o * 1568 + t] * map_b[t & 7];
#pragma unroll
            for (int s = 16; s; s >>= 1)
                acc += __shfl_xor_sync(0xFFFFFFFFu, acc, s);
            if (lane == 0) g_b2[o] = acc + lin_b[o];
        }
    } else {
        if (tid < 4) {
            float v0 = var_params[tid];
            float v1 = var_params[4 + tid];
            g_trig[tid]      = cosf(v0);
            g_trig[4 + tid]  = sinf(v0);
            g_trig[8 + tid]  = cosf(v1);
            g_trig[12 + tid] = sinf(v1);
        }
    }
}

// ---------------------------------------------------------------------------
// Fused kernel: per-patch circuit -> immediate accumulation against W2 (smem)
// Lane = (img_in_warp << 3) | seg.  Each lane: one image, patches p = seg+8k.
// W2 LDS is conflict-free: bank offset 12*seg mod 32 hits 8 distinct banks,
// 4 images broadcast each.
// ---------------------------------------------------------------------------
__global__ __launch_bounds__(256)
void quanv_kernel(const float* __restrict__ x, float* __restrict__ out) {
    __shared__ float W2s[W2_FLOATS];

    int tid = threadIdx.x;
    for (int idx = tid; idx < W2_FLOATS; idx += 256)
        W2s[idx] = g_W2[idx];

    // Trig constants to registers
    float cv0[4], sv0[4], cwv[4], swv[4];
#pragma unroll
    for (int j = 0; j < 4; j++) {
        cv0[j] = g_trig[j];
        sv0[j] = g_trig[4 + j];
        cwv[j] = g_trig[8 + j];
        swv[j] = g_trig[12 + j];
    }
    __syncthreads();

    int w    = tid >> 5;
    int lane = tid & 31;
    int seg  = lane & 7;
    int img  = (blockIdx.x * 8 + w) * 4 + (lane >> 3);

    const float* imgp = x + (size_t)img * 784;

    float acc[10];
#pragma unroll
    for (int o = 0; o < 10; o++) acc[o] = 0.0f;

    // Incremental patch coordinates (no divisions in the loop)
    int pr = 0, pc = seg;          // patch row/col in 14x14 grid
#pragma unroll 2
    for (int p = seg; p < 196; p += 8) {
        const float* base = imgp + pr * 56 + pc * 2;
        float2 r0 = *reinterpret_cast<const float2*>(base);
        float2 r1 = *reinterpret_cast<const float2*>(base + 28);

        // advance coords for next iteration
        pc += 8;
        if (pc >= 14) { pc -= 14; pr += 1; }

        float av[4] = {r0.x, r0.y, r1.x, r1.y};
        float C[4], S[4];
#pragma unroll
        for (int j = 0; j < 4; j++) {
            float t  = av[j] * (1.0f / 255.0f);          // < 0.004
            float t2 = t * t;
            float sa = t * (1.0f - t2 * (1.0f / 6.0f));  // sin(t) to fp32 ulp
            float ca = 1.0f - 0.5f * t2;                 // cos(t) to fp32 ulp
            C[j] = cv0[j] * ca - sv0[j] * sa;            // cos(t + v0)
            S[j] = sv0[j] * ca + cv0[j] * sa;            // sin(t + v0)
        }
        float P0 = C[0];
        float P1 = P0 * C[1];
        float P2 = P1 * C[2];
        float P3 = P2 * C[3];
        float z0 = cwv[0] * P0 - swv[0] * (S[0] * S[1]);
        float z1 = cwv[1] * P1 - swv[1] * (S[1] * S[2]);
        float z2 = cwv[2] * P2 - swv[2] * (S[2] * S[3]);
        float z3 = cwv[3] * P3 - swv[3] * S[3];

        const float* wr = &W2s[p * (4 * W2_STRIDE)];     // row i = 4p
#pragma unroll
        for (int o = 0; o < 10; o++) {
            float a = acc[o];
            a += z0 * wr[o];
            a += z1 * wr[W2_STRIDE + o];
            a += z2 * wr[2 * W2_STRIDE + o];
            a += z3 * wr[3 * W2_STRIDE + o];
            acc[o] = a;
        }
    }

    // Reduce across the 8 segments of this image (lanes img*8 .. img*8+7)
#pragma unroll
    for (int o = 0; o < 10; o++) {
        acc[o] += __shfl_xor_sync(0xFFFFFFFFu, acc[o], 1);
        acc[o] += __shfl_xor_sync(0xFFFFFFFFu, acc[o], 2);
        acc[o] += __shfl_xor_sync(0xFFFFFFFFu, acc[o], 4);
    }

    // Bias + log_softmax, one lane per image
    if (seg == 0) {
        float l[10];
        float mx = -1e30f;
#pragma unroll
        for (int o = 0; o < 10; o++) {
            l[o] = acc[o] + g_b2[o];
            mx = fmaxf(mx, l[o]);
        }
        float sum = 0.0f;
#pragma unroll
        for (int o = 0; o < 10; o++)
            sum += __expf(l[o] - mx);
        float lse = mx + __logf(sum);
        float* op = out + (size_t)img * 10;
#pragma unroll
        for (int o = 0; o < 10; o++)
            op[o] = l[o] - lse;
    }
}

// ---------------------------------------------------------------------------
extern "C" void kernel_launch(void* const* d_in, const int* in_sizes, int n_in,
                              void* d_out, int out_size) {
    const float* x          = (const float*)d_in[0];
    const float* var_params = (const float*)d_in[1];
    const float* map_w      = (const float*)d_in[2];
    const float* map_b      = (const float*)d_in[3];
    const float* lin_w      = (const float*)d_in[4];
    const float* lin_b      = (const float*)d_in[5];
    float* out = (float*)d_out;

    setup_kernel<<<33, 256>>>(var_params, map_w, map_b, lin_w, lin_b);
    quanv_kernel<<<GRID, 256>>>(x, out);
}

// round 3
// speedup vs baseline: 1.2979x; 1.2979x over previous
#include <cuda_runtime.h>
#include <cuda_bf16.h>

// Config: one warp per image, 32 patch-segments per lane.
// Block = 8 warps = 8 images; grid = 8192/8 = 1024.
#define P_STRIDE 41                       // 40 payload floats + 1 pad (ODD -> conflict-free)
#define W2_FLOATS (196 * P_STRIDE)        // 8036 floats = 31.4 KB
#define B_TOTAL 8192
#define IMGS_PER_BLOCK 8
#define GRID (B_TOTAL / IMGS_PER_BLOCK)   // 1024

// Scratch (no allocation allowed)
__device__ float g_W2[W2_FLOATS];   // [p][o][j] + pad: off = p*41 + o*4 + j
__device__ float g_b2[10];
__device__ float g_trig[16];        // cv0[0..3] sv0[4..7] cw[8..11] sw[12..15]

// ---------------------------------------------------------------------------
// Setup: fold map_w into lin_w (W2), fold map_b/lin_b into b2, precompute trig
// W2[p][o][j] = sum_k lin_w[o, 8p+k] * map_w[k, j]
// ---------------------------------------------------------------------------
__global__ void setup_kernel(const float* __restrict__ var_params,
                             const float* __restrict__ map_w,
                             const float* __restrict__ map_b,
                             const float* __restrict__ lin_w,
                             const float* __restrict__ lin_b) {
    int blk = blockIdx.x;
    int tid = threadIdx.x;
    if (blk < 31) {
        int idx = blk * 256 + tid;          // 0..7839
        if (idx < 7840) {
            int p = idx / 40;
            int r = idx - p * 40;           // r = o*4 + j
            int o = r >> 2;
            int j = r & 3;
            const float* lw = lin_w + o * 1568 + 8 * p;
            float acc = 0.0f;
#pragma unroll
            for (int k = 0; k < 8; k++)
                acc += lw[k] * map_w[k * 4 + j];
            g_W2[p * P_STRIDE + r] = acc;
        }
    } else if (blk == 31) {
        // b2[o] = lin_b[o] + sum_t lin_w[o, t] * map_b[t % 8]
        int w = tid >> 5, lane = tid & 31;
        for (int o = w; o < 10; o += 8) {
            float acc = 0.0f;
            for (int t = lane; t < 1568; t += 32)
                acc += lin_w[o * 1568 + t] * map_b[t & 7];
#pragma unroll
            for (int s = 16; s; s >>= 1)
                acc += __shfl_xor_sync(0xFFFFFFFFu, acc, s);
            if (lane == 0) g_b2[o] = acc + lin_b[o];
        }
    } else {
        if (tid < 4) {
            float v0 = var_params[tid];
            float v1 = var_params[4 + tid];
            g_trig[tid]      = cosf(v0);
            g_trig[4 + tid]  = sinf(v0);
            g_trig[8 + tid]  = cosf(v1);
            g_trig[12 + tid] = sinf(v1);
        }
    }
}

// ---------------------------------------------------------------------------
// Fused kernel. Warp = 1 image; lane = patch segment (p = lane + 32k).
// W2 smem: addr = 41*p + const -> bank = 9*lane mod 32, injective over 32
// lanes (9 is a unit mod 32) -> conflict-free, full 128B crossbar per LDS.
// ---------------------------------------------------------------------------
__global__ __launch_bounds__(256, 4)
void quanv_kernel(const float* __restrict__ x, float* __restrict__ out) {
    __shared__ float W2s[W2_FLOATS];

    int tid = threadIdx.x;
    for (int idx = tid; idx < W2_FLOATS; idx += 256)
        W2s[idx] = g_W2[idx];

    // Trig constants to registers (uniform across block)
    float cv0[4], sv0[4], cwv[4], swv[4];
#pragma unroll
    for (int j = 0; j < 4; j++) {
        cv0[j] = g_trig[j];
        sv0[j] = g_trig[4 + j];
        cwv[j] = g_trig[8 + j];
        swv[j] = g_trig[12 + j];
    }
    __syncthreads();

    int w    = tid >> 5;
    int lane = tid & 31;
    int img  = blockIdx.x * IMGS_PER_BLOCK + w;

    const float* imgp = x + (size_t)img * 784;

    float acc[10];
#pragma unroll
    for (int o = 0; o < 10; o++) acc[o] = 0.0f;

    // Initial patch coordinates for p = lane (14x14 patch grid)
    int pr = lane / 14;
    int pc = lane - pr * 14;

    // p = lane + 32k; segs 0..3 run 7 iterations, segs 4..31 run 6.
    for (int p = lane; p < 196; p += 32) {
        const float* base = imgp + pr * 56 + pc * 2;
        float2 r0 = *reinterpret_cast<const float2*>(base);
        float2 r1 = *reinterpret_cast<const float2*>(base + 28);

        // advance coords: p += 32 -> pc += 32 (= +2 rows, +4 cols)
        pr += 2; pc += 4;
        if (pc >= 14) { pc -= 14; pr += 1; }

        float av[4] = {r0.x, r0.y, r1.x, r1.y};
        float C[4], S[4];
#pragma unroll
        for (int j = 0; j < 4; j++) {
            float t  = av[j] * (1.0f / 255.0f);          // < 0.004
            float t2 = t * t;
            float sa = t * (1.0f - t2 * (1.0f / 6.0f));  // sin(t) to fp32 ulp
            float ca = 1.0f - 0.5f * t2;                 // cos(t) to fp32 ulp
            C[j] = cv0[j] * ca - sv0[j] * sa;            // cos(t + v0)
            S[j] = sv0[j] * ca + cv0[j] * sa;            // sin(t + v0)
        }
        float P0 = C[0];
        float P1 = P0 * C[1];
        float P2 = P1 * C[2];
        float P3 = P2 * C[3];
        float z0 = cwv[0] * P0 - swv[0] * (S[0] * S[1]);
        float z1 = cwv[1] * P1 - swv[1] * (S[1] * S[2]);
        float z2 = cwv[2] * P2 - swv[2] * (S[2] * S[3]);
        float z3 = cwv[3] * P3 - swv[3] * S[3];

        const float* wr = &W2s[p * P_STRIDE];    // [o][j] payload, 40 floats
#pragma unroll
        for (int o = 0; o < 10; o++) {
            float a = acc[o];
            a += z0 * wr[o * 4 + 0];
            a += z1 * wr[o * 4 + 1];
            a += z2 * wr[o * 4 + 2];
            a += z3 * wr[o * 4 + 3];
            acc[o] = a;
        }
    }

    // Full-warp butterfly reduce: every lane ends with the image's 10 logits
#pragma unroll
    for (int o = 0; o < 10; o++) {
#pragma unroll
        for (int s = 16; s; s >>= 1)
            acc[o] += __shfl_xor_sync(0xFFFFFFFFu, acc[o], s);
    }

    // Bias + log_softmax, lane 0 writes
    if (lane == 0) {
        float l[10];
        float mx = -1e30f;
#pragma unroll
        for (int o = 0; o < 10; o++) {
            l[o] = acc[o] + g_b2[o];
            mx = fmaxf(mx, l[o]);
        }
        float sum = 0.0f;
#pragma unroll
        for (int o = 0; o < 10; o++)
            sum += __expf(l[o] - mx);
        float lse = mx + __logf(sum);
        float* op = out + (size_t)img * 10;
#pragma unroll
        for (int o = 0; o < 10; o++)
            op[o] = l[o] - lse;
    }
}

// ---------------------------------------------------------------------------
extern "C" void kernel_launch(void* const* d_in, const int* in_sizes, int n_in,
                              void* d_out, int out_size) {
    const float* x          = (const float*)d_in[0];
    const float* var_params = (const float*)d_in[1];
    const float* map_w      = (const float*)d_in[2];
    const float* map_b      = (const float*)d_in[3];
    const float* lin_w      = (const float*)d_in[4];
    const float* lin_b      = (const float*)d_in[5];
    float* out = (float*)d_out;

    setup_kernel<<<33, 256>>>(var_params, map_w, map_b, lin_w, lin_b);
    quanv_kernel<<<GRID, 256>>>(x, out);
}

// round 4
// speedup vs baseline: 1.6962x; 1.3069x over previous
#include <cuda_runtime.h>
#include <cuda_bf16.h>

#define P_STRIDE 42                     // 40 payload + 2 pad; 42=4*? -> 21 granules, odd mod 16
#define A_FLOATS (196 * P_STRIDE)       // 8232 floats = 32.9 KB
#define B_TOTAL 8192
#define GRID_MAIN 512                   // 8 warps * 2 imgs = 16 imgs / block

// Scratch (no allocation allowed)
__device__ __align__(16) float g_A[A_FLOATS];   // [p][i][o]: off = p*42 + i*10 + o
__device__ float g_c[10];

// ---- f32x2 helpers -------------------------------------------------------
__device__ __forceinline__ unsigned long long dup2(float v) {
    unsigned long long r;
    asm("mov.b64 %0, {%1, %1};" : "=l"(r) : "f"(v));
    return r;
}
__device__ __forceinline__ void fma2(unsigned long long& d, unsigned long long a,
                                     unsigned long long b) {
    asm("fma.rn.f32x2 %0, %1, %2, %0;" : "+l"(d) : "l"(a), "l"(b));
}
__device__ __forceinline__ unsigned long long add2(unsigned long long a,
                                                   unsigned long long b) {
    unsigned long long r;
    asm("add.rn.f32x2 %0, %1, %2;" : "=l"(r) : "l"(a), "l"(b));
    return r;
}
__device__ __forceinline__ void upk2(float& lo, float& hi, unsigned long long v) {
    asm("mov.b64 {%0, %1}, %2;" : "=f"(lo), "=f"(hi) : "l"(v));
}

// ---------------------------------------------------------------------------
// Setup: linearize the circuit around t=0 and fold everything into A, c.
//   meas_j(patch) ~= z0[j] + sum_i D[j][i] * t_i,  t_i = pixel_i / 255
//   A[p,i,o] = sum_k lin_w[o,8p+k] * E[k][i],  E[k][i] = (1/255) sum_j map_w[k,j] D[j][i]
//   c[o]     = lin_b[o] + sum_t lin_w[o,t] * q[t%8], q[k] = map_b[k] + sum_j map_w[k,j] z0[j]
// ---------------------------------------------------------------------------
__global__ void setup_kernel(const float* __restrict__ var_params,
                             const float* __restrict__ map_w,
                             const float* __restrict__ map_b,
                             const float* __restrict__ lin_w,
                             const float* __restrict__ lin_b) {
    __shared__ float Es[32];   // E[k][i]
    __shared__ float qs[8];
    int tid = threadIdx.x, blk = blockIdx.x;

    if (tid == 0) {
        float cv[4], sv[4], cw[4], sw[4];
#pragma unroll
        for (int j = 0; j < 4; j++) {
            sincosf(var_params[j],     &sv[j], &cv[j]);
            sincosf(var_params[4 + j], &sw[j], &cw[j]);
        }
        float D[4][4];
#pragma unroll
        for (int j = 0; j < 4; j++)
#pragma unroll
            for (int i = 0; i < 4; i++) D[j][i] = 0.0f;
        // z0 = cw0*C0 - sw0*S0S1 ; z1 = cw1*C0C1 - sw1*S1S2 ;
        // z2 = cw2*C0C1C2 - sw2*S2S3 ; z3 = cw3*C0C1C2C3 - sw3*S3
        D[0][0] = -cw[0]*sv[0] - sw[0]*cv[0]*sv[1];
        D[0][1] = -sw[0]*sv[0]*cv[1];
        D[1][0] = -cw[1]*sv[0]*cv[1];
        D[1][1] = -cw[1]*cv[0]*sv[1] - sw[1]*cv[1]*sv[2];
        D[1][2] = -sw[1]*sv[1]*cv[2];
        D[2][0] = -cw[2]*sv[0]*cv[1]*cv[2];
        D[2][1] = -cw[2]*cv[0]*sv[1]*cv[2];
        D[2][2] = -cw[2]*cv[0]*cv[1]*sv[2] - sw[2]*cv[2]*sv[3];
        D[2][3] = -sw[2]*sv[2]*cv[3];
        float P2c = cv[0]*cv[1]*cv[2];
        D[3][0] = -cw[3]*sv[0]*cv[1]*cv[2]*cv[3];
        D[3][1] = -cw[3]*cv[0]*sv[1]*cv[2]*cv[3];
        D[3][2] = -cw[3]*cv[0]*cv[1]*sv[2]*cv[3];
        D[3][3] = -cw[3]*P2c*sv[3] - sw[3]*cv[3];
        float z0v[4];
        z0v[0] = cw[0]*cv[0]            - sw[0]*sv[0]*sv[1];
        z0v[1] = cw[1]*cv[0]*cv[1]      - sw[1]*sv[1]*sv[2];
        z0v[2] = cw[2]*P2c              - sw[2]*sv[2]*sv[3];
        z0v[3] = cw[3]*P2c*cv[3]        - sw[3]*sv[3];
#pragma unroll
        for (int k = 0; k < 8; k++) {
            float q = map_b[k];
#pragma unroll
            for (int j = 0; j < 4; j++) q += map_w[k*4 + j] * z0v[j];
            qs[k] = q;
#pragma unroll
            for (int i = 0; i < 4; i++) {
                float e = 0.0f;
#pragma unroll
                for (int j = 0; j < 4; j++) e += map_w[k*4 + j] * D[j][i];
                Es[k*4 + i] = e * (1.0f / 255.0f);
            }
        }
    }
    __syncthreads();

    if (blk < 31) {
        int idx = blk * 256 + tid;              // 0..7839 -> (p, i, o)
        if (idx < 7840) {
            int p = idx / 40;
            int r = idx - 40 * p;
            int i = r / 10;
            int o = r - 10 * i;
            const float* lw = lin_w + o * 1568 + 8 * p;
            float acc = 0.0f;
#pragma unroll
            for (int k = 0; k < 8; k++) acc += lw[k] * Es[k*4 + i];
            g_A[p * P_STRIDE + i * 10 + o] = acc;
        }
    } else {
        int w = tid >> 5, lane = tid & 31;
        for (int o = w; o < 10; o += 8) {
            float acc = 0.0f;
            for (int t = lane; t < 1568; t += 32)
                acc += lin_w[o * 1568 + t] * qs[t & 7];
#pragma unroll
            for (int s = 16; s; s >>= 1)
                acc += __shfl_xor_sync(0xFFFFFFFFu, acc, s);
            if (lane == 0) g_c[o] = acc + lin_b[o];
        }
    }
}

// ---------------------------------------------------------------------------
// Main: logits = x . A^T + c, then log_softmax.  Warp = 2 consecutive images;
// lane owns patches p = lane + 32k.  A in smem, stride 42 floats/patch ->
// LDS.64 of o-pairs is conflict-free (21*L mod 16 injective over any phase).
// ---------------------------------------------------------------------------
__global__ __launch_bounds__(256, 4)
void main_kernel(const float* __restrict__ x, float* __restrict__ out) {
    __shared__ __align__(16) float As[A_FLOATS];

    int tid = threadIdx.x;
    {
        const float4* src = reinterpret_cast<const float4*>(g_A);
        float4* dst = reinterpret_cast<float4*>(As);
        for (int i = tid; i < A_FLOATS / 4; i += 256) dst[i] = src[i];
    }
    __syncthreads();

    int w    = tid >> 5;
    int lane = tid & 31;
    int imgA = (blockIdx.x * 8 + w) * 2;
    const float* pa = x + (size_t)imgA * 784;
    const float* pb = pa + 784;

    unsigned long long accA[5], accB[5];
#pragma unroll
    for (int q = 0; q < 5; q++) { accA[q] = 0ull; accB[q] = 0ull; }

    int pr = lane / 14;
    int pc = lane - pr * 14;

#pragma unroll 2
    for (int k = 0; k < 6; k++) {               // p = lane + 32k, all < 192
        int p   = lane + 32 * k;
        int off = pr * 56 + pc * 2;
        float2 a0 = *reinterpret_cast<const float2*>(pa + off);
        float2 a1 = *reinterpret_cast<const float2*>(pa + off + 28);
        float2 b0 = *reinterpret_cast<const float2*>(pb + off);
        float2 b1 = *reinterpret_cast<const float2*>(pb + off + 28);
        pr += 2; pc += 4;
        if (pc >= 14) { pc -= 14; pr += 1; }

        unsigned long long xa[4] = {dup2(a0.x), dup2(a0.y), dup2(a1.x), dup2(a1.y)};
        unsigned long long xb[4] = {dup2(b0.x), dup2(b0.y), dup2(b1.x), dup2(b1.y)};

        const float* wr = &As[p * P_STRIDE];
#pragma unroll
        for (int i = 0; i < 4; i++) {
            const unsigned long long* wp =
                reinterpret_cast<const unsigned long long*>(wr + i * 10);
#pragma unroll
            for (int q = 0; q < 5; q++) {
                unsigned long long wv = wp[q];
                fma2(accA[q], wv, xa[i]);
                fma2(accB[q], wv, xb[i]);
            }
        }
    }

    // Tail: patches 192..195 handled by lanes 0..3
    if (lane < 4) {
        int p   = 192 + lane;
        int off = 13 * 56 + (10 + lane) * 2;
        float2 a0 = *reinterpret_cast<const float2*>(pa + off);
        float2 a1 = *reinterpret_cast<const float2*>(pa + off + 28);
        float2 b0 = *reinterpret_cast<const float2*>(pb + off);
        float2 b1 = *reinterpret_cast<const float2*>(pb + off + 28);
        unsigned long long xa[4] = {dup2(a0.x), dup2(a0.y), dup2(a1.x), dup2(a1.y)};
        unsigned long long xb[4] = {dup2(b0.x), dup2(b0.y), dup2(b1.x), dup2(b1.y)};
        const float* wr = &As[p * P_STRIDE];
#pragma unroll
        for (int i = 0; i < 4; i++) {
            const unsigned long long* wp =
                reinterpret_cast<const unsigned long long*>(wr + i * 10);
#pragma unroll
            for (int q = 0; q < 5; q++) {
                unsigned long long wv = wp[q];
                fma2(accA[q], wv, xa[i]);
                fma2(accB[q], wv, xb[i]);
            }
        }
    }

    // Packed butterfly reduce across the warp (both images at once)
#pragma unroll
    for (int q = 0; q < 5; q++) {
#pragma unroll
        for (int s = 16; s; s >>= 1) {
            accA[q] = add2(accA[q], __shfl_xor_sync(0xFFFFFFFFu, accA[q], s));
            accB[q] = add2(accB[q], __shfl_xor_sync(0xFFFFFFFFu, accB[q], s));
        }
    }

    // Lane 0 -> image A, lane 1 -> image B
    if (lane < 2) {
        unsigned long long sel[5];
#pragma unroll
        for (int q = 0; q < 5; q++) sel[q] = lane ? accB[q] : accA[q];
        float l[10];
#pragma unroll
        for (int q = 0; q < 5; q++) upk2(l[2*q], l[2*q + 1], sel[q]);
        float mx = -1e30f;
#pragma unroll
        for (int o = 0; o < 10; o++) {
            l[o] += g_c[o];
            mx = fmaxf(mx, l[o]);
        }
        float sum = 0.0f;
#pragma unroll
        for (int o = 0; o < 10; o++) sum += __expf(l[o] - mx);
        float lse = mx + __logf(sum);
        float* op = out + (size_t)(imgA + lane) * 10;
#pragma unroll
        for (int o = 0; o < 10; o++) op[o] = l[o] - lse;
    }
}

// ---------------------------------------------------------------------------
extern "C" void kernel_launch(void* const* d_in, const int* in_sizes, int n_in,
                              void* d_out, int out_size) {
    const float* x          = (const float*)d_in[0];
    const float* var_params = (const float*)d_in[1];
    const float* map_w      = (const float*)d_in[2];
    const float* map_b      = (const float*)d_in[3];
    const float* lin_w      = (const float*)d_in[4];
    const float* lin_b      = (const float*)d_in[5];
    float* out = (float*)d_out;

    setup_kernel<<<32, 256>>>(var_params, map_w, map_b, lin_w, lin_b);
    main_kernel<<<GRID_MAIN, 256>>>(x, out);
}